// round 17
// baseline (speedup 1.0000x reference)
#include <cuda_runtime.h>

#define DIM   768
#define POOL  20
#define TOPK  9
#define NVEC  6                 // float4 chunks per lane: 768 / 4 / 32
#define WARPS 8
#define ROWS_PER_BLOCK WARPS    // 8: one row per warp

// Allocation-free scratch
__device__ float        g_kn[POOL * DIM];
__device__ float        g_rowsum[POOL];
__device__ unsigned int g_count[POOL];

// ---------------------------------------------------------------------------
// prep: 1 block x 640 threads. Warp w normalizes key row w (shuffle-only).
// Re-zeros accumulators every replay (graph determinism).
// ---------------------------------------------------------------------------
__global__ void prep_kernel(const float* __restrict__ keys,
                            const int*   __restrict__ layer)
{
    const int w    = threadIdx.x >> 5;
    const int lane = threadIdx.x & 31;

    if (w < POOL) {
        const float* __restrict__ krow =
            keys + ((size_t)(*layer) * POOL + w) * DIM;
        float ss = 0.f;
        #pragma unroll
        for (int i = 0; i < DIM / 32; i++) {
            float v = __ldg(krow + lane + 32 * i);
            ss += v * v;
        }
        #pragma unroll
        for (int off = 16; off; off >>= 1)
            ss += __shfl_xor_sync(0xffffffffu, ss, off);
        const float inv = 1.f / fmaxf(sqrtf(ss), 1e-12f);
        #pragma unroll
        for (int i = 0; i < DIM / 32; i++)
            g_kn[w * DIM + lane + 32 * i] = __ldg(krow + lane + 32 * i) * inv;
    }
    if (threadIdx.x < POOL) {
        g_count[threadIdx.x]  = 0u;
        g_rowsum[threadIdx.x] = 0.f;
    }
}

// ---------------------------------------------------------------------------
// main: ONE row per warp, 42-reg cap -> 6 CTAs/SM (48 warps). Probing the
// next point on the measured occupancy gradient.
// ---------------------------------------------------------------------------
__global__ void __launch_bounds__(256, 6)
pool_main(const float* __restrict__ x,
          const float* __restrict__ prompts,
          const int*   __restrict__ layer,
          float*       __restrict__ out,
          int B)
{
    __shared__ unsigned int s_count[POOL];
    if (threadIdx.x < POOL) s_count[threadIdx.x] = 0u;
    __syncthreads();

    const int warp = threadIdx.x >> 5;
    const int lane = threadIdx.x & 31;
    const int row  = blockIdx.x * ROWS_PER_BLOCK + warp;

    if (row < B) {
        const float4* __restrict__ xr  = (const float4*)(x + (size_t)row * DIM);
        const float4* __restrict__ knv = (const float4*)g_kn;

        float s[POOL];
        #pragma unroll
        for (int j = 0; j < POOL; j++) s[j] = 0.f;
        float ss = 0.f;

        #pragma unroll
        for (int i = 0; i < NVEC; i++) {
            // streaming load: evict-first, keep keys/prompts resident in L1
            const float4 xv = __ldcs(xr + lane + 32 * i);
            ss += xv.x * xv.x + xv.y * xv.y + xv.z * xv.z + xv.w * xv.w;
            #pragma unroll
            for (int j = 0; j < POOL; j++) {
                const float4 kv = __ldg(knv + j * (DIM / 4) + lane + 32 * i);
                s[j] += xv.x * kv.x + xv.y * kv.y + xv.z * kv.z + xv.w * kv.w;
            }
        }

        // butterfly reduce 21 accumulators
        #pragma unroll
        for (int off = 16; off; off >>= 1) {
            ss += __shfl_xor_sync(0xffffffffu, ss, off);
            #pragma unroll
            for (int j = 0; j < POOL; j++)
                s[j] += __shfl_xor_sync(0xffffffffu, s[j], off);
        }

        const float inv = 1.f / fmaxf(sqrtf(ss), 1e-12f);
        #pragma unroll
        for (int j = 0; j < POOL; j++) s[j] *= inv;

        // dist bookkeeping: pool-sum of sim rows 0..19
        if (lane == 0 && row < POOL) {
            float rs = 0.f;
            #pragma unroll
            for (int j = 0; j < POOL; j++) rs += s[j];
            g_rowsum[row] = rs;
        }

        // iterative top-9 (strict '>' => lower index wins ties, matches lax.top_k)
        int idx[TOPK];
        #pragma unroll
        for (int t = 0; t < TOPK; t++) {
            float best = -3.4e38f; int bj = 0;
            #pragma unroll
            for (int j = 0; j < POOL; j++)
                if (s[j] > best) { best = s[j]; bj = j; }
            idx[t] = bj;
            #pragma unroll
            for (int j = 0; j < POOL; j++)
                if (j == bj) s[j] = -3.4e38f;
        }

        if (lane == 0) {
            #pragma unroll
            for (int t = 0; t < TOPK; t++)
                atomicAdd(&s_count[idx[t]], 1u);
        }

        // gather: 9 prompt-row copies, coalesced streaming stores
        const float4* __restrict__ pbase =
            (const float4*)(prompts + (size_t)(*layer) * POOL * DIM);
        float4* __restrict__ orow = (float4*)out + (size_t)row * (TOPK * DIM / 4);
        #pragma unroll
        for (int t = 0; t < TOPK; t++) {
            const float4* pr = pbase + idx[t] * (DIM / 4);
            #pragma unroll
            for (int i = 0; i < NVEC; i++)
                __stcs(orow + t * (DIM / 4) + lane + 32 * i,
                       __ldg(pr + lane + 32 * i));
        }
    }

    __syncthreads();
    if (threadIdx.x < POOL)
        atomicAdd(&g_count[threadIdx.x], s_count[threadIdx.x]);
}

// ---------------------------------------------------------------------------
// finalize: dist = 1 - sum_r count[r]*rowsum[r] / (B*TOPK*POOL)
// ---------------------------------------------------------------------------
__global__ void finalize_kernel(float* __restrict__ out,
                                long long total, long long out_size, int B)
{
    double s = 0.0;
    #pragma unroll
    for (int r = 0; r < POOL; r++)
        s += (double)g_count[r] * (double)g_rowsum[r];
    const float dist = (float)(1.0 - s / ((double)B * TOPK * POOL));
    for (long long i = total + threadIdx.x; i < out_size; i += blockDim.x)
        out[i] = dist;
}

extern "C" void kernel_launch(void* const* d_in, const int* in_sizes, int n_in,
                              void* d_out, int out_size)
{
    const float* x       = (const float*)d_in[0];
    const float* keys    = (const float*)d_in[1];
    const float* prompts = (const float*)d_in[2];
    const int*   layer   = (const int*)d_in[3];

    const int B = in_sizes[0] / DIM;
    const long long total = (long long)B * TOPK * DIM;

    prep_kernel<<<1, 640>>>(keys, layer);
    pool_main<<<(B + ROWS_PER_BLOCK - 1) / ROWS_PER_BLOCK, 256>>>(
        x, prompts, layer, (float*)d_out, B);
    finalize_kernel<<<1, 32>>>((float*)d_out, total, (long long)out_size, B);
}